// round 14
// baseline (speedup 1.0000x reference)
#include <cuda_runtime.h>
#include <cstdint>

#define B_  64
#define OH_ 120
#define OW_ 160
#define HW_ (OH_ * OW_)          // 19200
#define TOTAL_ (B_ * HW_)        // 1,228,800
#define IN_H_ 480.0f
#define IN_W_ 640.0f
#define THRESH_ 0.5f

#define NT  128                  // 4 warps
#define NW  (NT / 32)
#define PPT 2                    // pixels per thread
#define PPW 64                   // pixels per warp
#define PPB (NT * PPT)           // 256 pixels per block

// 15 CTAs/SM: 15*15KB = 225KB smem (<=228), 15*128*32 = 61440 regs -> 60 warps (94%)
__global__ __launch_bounds__(NT, 15)
void centerface_decode_kernel(const float* __restrict__ heatmap,   // [B,1,OH,OW]
                              const float* __restrict__ scale,     // [B,2,OH,OW]
                              const float* __restrict__ offset,    // [B,2,OH,OW]
                              const float* __restrict__ landmark,  // [B,10,OH,OW]
                              float* __restrict__ boxes,           // [B,HW,5]
                              float* __restrict__ lms,             // [B,HW,10]
                              float* __restrict__ keep)            // [B,HW]
{
    // Separate buffers: no phase reuse -> no WAR hazard -> ONE sync, one
    // merged dependency-free store run (max store MLP per warp).
    __shared__ float box_s[NW][PPW * 5];    // 5 KB
    __shared__ float lm_s [NW][PPW * 10];   // 10 KB

    const int tid  = threadIdx.x;
    const int wid  = tid >> 5;
    const int lane = tid & 31;

    const int base     = blockIdx.x * PPB;
    const int warpbase = base + wid * PPW;
    const int idx0     = warpbase + lane * PPT;

    const int b  = idx0 / HW_;
    const int p0 = idx0 - b * HW_;
    const int y  = p0 / OW_;
    const float yf = (float)y;

    // ---- vector loads (cached: inputs stay L2-resident across graph replays) ----
    union F2 { float2 v; float a[2]; };
    F2 hm, sc0, sc1, o0;
    hm.v  = *(const float2*)(heatmap + idx0);
    const float* scp = scale + (size_t)b * (2 * HW_) + p0;
    sc0.v = *(const float2*)(scp);
    sc1.v = *(const float2*)(scp + HW_);
    o0.v  = *(const float2*)(offset + (size_t)b * (2 * HW_) + p0);

    F2 lm[10];
    const float* lmp = landmark + (size_t)b * (10 * HW_) + p0;
#pragma unroll
    for (int j = 0; j < 10; j++)
        lm[j].v = *(const float2*)(lmp + (size_t)j * HW_);

    // ---- per-pixel compute: stage boxes AND landmarks ----
    F2 kp;
    float* bs = box_s[wid] + lane * (5 * PPT);             // 10 contiguous floats
    float2* ls = (float2*)(lm_s[wid] + lane * (10 * PPT)); // 20 contiguous floats

#pragma unroll
    for (int q = 0; q < PPT; q++) {
        float s0 = __expf(sc0.a[q]) * 4.0f;
        float s1 = __expf(sc1.a[q]) * 4.0f;

        float y1_raw = (yf + o0.a[q] + 0.5f) * 4.0f - s0 * 0.5f;
        float y1c = fmaxf(y1_raw, 0.0f);
        float y1  = fminf(y1c, IN_H_);
        float x1  = fminf(y1c, IN_W_);
        float y2  = fminf(y1 + s0, IN_H_);
        float x2  = fminf(x1 + s1, IN_W_);

        float h = hm.a[q];
        float m = (h >= THRESH_) ? 1.0f : 0.0f;
        kp.a[q] = m;

        // stage box record (vector STS where alignment allows: bs 8B-aligned)
        float2* bq2 = (float2*)(bs + q * 5 + (q & 1));
        if (q == 0) {
            bq2[0] = make_float2(x1 * m, y1 * m);
            bq2[1] = make_float2(x2 * m, y2 * m);
            bs[4]  = h * m;
        } else {
            bs[5]  = x1 * m;
            bq2[0] = make_float2(y1 * m, x2 * m);
            bq2[1] = make_float2(y2 * m, h * m);
        }

        // stage landmark record
#pragma unroll
        for (int j = 0; j < 10; j += 2) {
            float ly = fmaf(lm[j].a[q],     s0, y1) * m;
            float lx = fmaf(lm[j + 1].a[q], s1, x1) * m;
            ls[q * 5 + (j >> 1)] = make_float2(ly, lx);
        }
    }

    // keep: coalesced STG.64
    *(float2*)(keep + idx0) = kp.v;

    __syncwarp();   // single phase boundary

    // ---- merged flush: 7.5 STG.128 per lane, one dependency-free run,
    //      streaming (evict-first: outputs never re-read) ----
    {
        const float4* bsrc = (const float4*)box_s[wid];   // 80 float4
        const float4* lsrc = (const float4*)lm_s[wid];    // 160 float4
        float4* bdst = (float4*)(boxes + (size_t)warpbase * 5);
        float4* ldst = (float4*)(lms   + (size_t)warpbase * 10);

        __stcs(bdst + lane,       bsrc[lane]);
        __stcs(ldst + lane,       lsrc[lane]);
        __stcs(bdst + 32 + lane,  bsrc[32 + lane]);
        __stcs(ldst + 32 + lane,  lsrc[32 + lane]);
        __stcs(ldst + 64 + lane,  lsrc[64 + lane]);
        __stcs(ldst + 96 + lane,  lsrc[96 + lane]);
        __stcs(ldst + 128 + lane, lsrc[128 + lane]);
        if (lane < 16) __stcs(bdst + 64 + lane, bsrc[64 + lane]);
    }
}

extern "C" void kernel_launch(void* const* d_in, const int* in_sizes, int n_in,
                              void* d_out, int out_size)
{
    const float* heatmap  = (const float*)d_in[0];
    const float* scale    = (const float*)d_in[1];
    const float* offset   = (const float*)d_in[2];
    const float* landmark = (const float*)d_in[3];

    float* out   = (float*)d_out;
    float* boxes = out;                          // [B,HW,5]
    float* lms   = out + (size_t)TOTAL_ * 5;     // [B,HW,10]
    float* keep  = out + (size_t)TOTAL_ * 15;    // [B,HW]

    int blocks = TOTAL_ / PPB;                   // 4800
    centerface_decode_kernel<<<blocks, NT>>>(heatmap, scale, offset, landmark,
                                             boxes, lms, keep);
}

// round 15
// speedup vs baseline: 1.0743x; 1.0743x over previous
#include <cuda_runtime.h>
#include <cstdint>

#define B_  64
#define OH_ 120
#define OW_ 160
#define HW_ (OH_ * OW_)          // 19200
#define TOTAL_ (B_ * HW_)        // 1,228,800
#define IN_H_ 480.0f
#define IN_W_ 640.0f
#define THRESH_ 0.5f

#define NT  128                  // 4 warps
#define NW  (NT / 32)
#define PPT 2                    // pixels per thread
#define PPW 64                   // pixels per warp
#define PPB (NT * PPT)           // 256 pixels per block

#define NTILES (TOTAL_ / PPB)    // 4800 tiles
#define GRID_  2368              // 148 SMs * 16 CTAs: exactly one wave

// 16 CTAs/SM: 16*10KB = 160KB smem, 16*128*32 = 65536 regs -> 64 warps (100%)
__global__ __launch_bounds__(NT, 16)
void centerface_decode_kernel(const float* __restrict__ heatmap,   // [B,1,OH,OW]
                              const float* __restrict__ scale,     // [B,2,OH,OW]
                              const float* __restrict__ offset,    // [B,2,OH,OW]
                              const float* __restrict__ landmark,  // [B,10,OH,OW]
                              float* __restrict__ boxes,           // [B,HW,5]
                              float* __restrict__ lms,             // [B,HW,10]
                              float* __restrict__ keep)            // [B,HW]
{
    // One reusable staging buffer per warp: 640 floats = 2.5 KB.
    // Phase 1: boxes (first 1280 B). Phase 2: landmarks (all 2560 B).
    __shared__ float buf[NW][PPW * 10];     // 10 KB

    const int tid  = threadIdx.x;
    const int wid  = tid >> 5;
    const int lane = tid & 31;

    // Persistent CTA: grid-stride over tiles (2-3 tiles per CTA, single wave).
    #pragma unroll 1
    for (int blk = blockIdx.x; blk < NTILES; blk += GRID_) {

        __syncwarp();   // WAR across iterations: buffer fully read before reuse

        const int base     = blk * PPB;
        const int warpbase = base + wid * PPW;
        const int idx0     = warpbase + lane * PPT;

        const int b  = idx0 / HW_;
        const int p0 = idx0 - b * HW_;
        const int y  = p0 / OW_;
        const float yf = (float)y;

        // ---- vector loads (cached: inputs stay L2-resident across replays) ----
        union F2 { float2 v; float a[2]; };
        F2 hm, sc0, sc1, o0;
        hm.v  = *(const float2*)(heatmap + idx0);
        const float* scp = scale + (size_t)b * (2 * HW_) + p0;
        sc0.v = *(const float2*)(scp);
        sc1.v = *(const float2*)(scp + HW_);
        o0.v  = *(const float2*)(offset + (size_t)b * (2 * HW_) + p0);

        F2 lm[10];
        const float* lmp = landmark + (size_t)b * (10 * HW_) + p0;
#pragma unroll
        for (int j = 0; j < 10; j++)
            lm[j].v = *(const float2*)(lmp + (size_t)j * HW_);

        // ---- per-pixel compute, stage boxes ----
        F2 kp;
        float s0q[PPT], s1q[PPT], y1q[PPT], x1q[PPT], mq[PPT];

        float* bs = buf[wid] + lane * (5 * PPT);     // 10 contiguous floats

#pragma unroll
        for (int q = 0; q < PPT; q++) {
            float s0 = __expf(sc0.a[q]) * 4.0f;
            float s1 = __expf(sc1.a[q]) * 4.0f;

            float y1_raw = (yf + o0.a[q] + 0.5f) * 4.0f - s0 * 0.5f;
            float y1c = fmaxf(y1_raw, 0.0f);
            float y1  = fminf(y1c, IN_H_);
            float x1  = fminf(y1c, IN_W_);
            float y2  = fminf(y1 + s0, IN_H_);
            float x2  = fminf(x1 + s1, IN_W_);

            float h = hm.a[q];
            float m = (h >= THRESH_) ? 1.0f : 0.0f;
            kp.a[q] = m;

            s0q[q] = s0; s1q[q] = s1; y1q[q] = y1; x1q[q] = x1; mq[q] = m;

            // stage box record (vector STS where alignment allows)
            float2* bq2 = (float2*)(bs + q * 5 + (q & 1));
            if (q == 0) {
                bq2[0] = make_float2(x1 * m, y1 * m);
                bq2[1] = make_float2(x2 * m, y2 * m);
                bs[4]  = h * m;
            } else {
                bs[5]  = x1 * m;
                bq2[0] = make_float2(y1 * m, x2 * m);
                bq2[1] = make_float2(y2 * m, h * m);
            }
        }

        // keep: coalesced STG.64
        *(float2*)(keep + idx0) = kp.v;

        __syncwarp();

        // ---- flush boxes: 80 float4 per warp (streaming: evict-first) ----
        {
            const float4* src = (const float4*)buf[wid];
            float4*       dst = (float4*)(boxes + (size_t)warpbase * 5);
            __stcs(dst + lane,      src[lane]);
            __stcs(dst + 32 + lane, src[32 + lane]);
            if (lane < 16) __stcs(dst + 64 + lane, src[64 + lane]);
        }

        __syncwarp();   // WAR: box region fully read before landmark overwrite

        // ---- stage landmarks into same buffer ----
        {
            float2* ls = (float2*)(buf[wid] + lane * (10 * PPT));  // 20 floats
#pragma unroll
            for (int q = 0; q < PPT; q++) {
                float s0 = s0q[q], s1 = s1q[q], y1 = y1q[q], x1 = x1q[q], m = mq[q];
#pragma unroll
                for (int j = 0; j < 10; j += 2) {
                    float ly = fmaf(lm[j].a[q],     s0, y1) * m;
                    float lx = fmaf(lm[j + 1].a[q], s1, x1) * m;
                    ls[q * 5 + (j >> 1)] = make_float2(ly, lx);
                }
            }
        }

        __syncwarp();

        // ---- flush landmarks: 160 float4 per warp (streaming) ----
        {
            const float4* src = (const float4*)buf[wid];
            float4*       dst = (float4*)(lms + (size_t)warpbase * 10);
#pragma unroll
            for (int i = 0; i < 5; i++)
                __stcs(dst + i * 32 + lane, src[i * 32 + lane]);
        }
    }
}

extern "C" void kernel_launch(void* const* d_in, const int* in_sizes, int n_in,
                              void* d_out, int out_size)
{
    const float* heatmap  = (const float*)d_in[0];
    const float* scale    = (const float*)d_in[1];
    const float* offset   = (const float*)d_in[2];
    const float* landmark = (const float*)d_in[3];

    float* out   = (float*)d_out;
    float* boxes = out;                          // [B,HW,5]
    float* lms   = out + (size_t)TOTAL_ * 5;     // [B,HW,10]
    float* keep  = out + (size_t)TOTAL_ * 15;    // [B,HW]

    centerface_decode_kernel<<<GRID_, NT>>>(heatmap, scale, offset, landmark,
                                            boxes, lms, keep);
}

// round 16
// speedup vs baseline: 1.1620x; 1.0816x over previous
#include <cuda_runtime.h>
#include <cstdint>

#define B_  64
#define OH_ 120
#define OW_ 160
#define HW_ (OH_ * OW_)          // 19200
#define TOTAL_ (B_ * HW_)        // 1,228,800
#define IN_H_ 480.0f
#define IN_W_ 640.0f
#define THRESH_ 0.5f

#define NT  128                  // 4 warps
#define NW  (NT / 32)
#define PPT 2                    // pixels per thread
#define PPW 64                   // pixels per warp
#define PPB (NT * PPT)           // 256 pixels per block

// 16 CTAs/SM: 16*10KB = 160KB smem, 16*128*32 = 65536 regs -> 64 warps (100%)
__global__ __launch_bounds__(NT, 16)
void centerface_decode_kernel(const float* __restrict__ heatmap,   // [B,1,OH,OW]
                              const float* __restrict__ scale,     // [B,2,OH,OW]
                              const float* __restrict__ offset,    // [B,2,OH,OW]
                              const float* __restrict__ landmark,  // [B,10,OH,OW]
                              float* __restrict__ boxes,           // [B,HW,5]
                              float* __restrict__ lms,             // [B,HW,10]
                              float* __restrict__ keep)            // [B,HW]
{
    // One reusable staging buffer per warp: 640 floats = 2.5 KB.
    // Phase 1: boxes (first 1280 B). Phase 2: landmarks (all 2560 B).
    __shared__ float buf[NW][PPW * 10];     // 10 KB

    const int tid  = threadIdx.x;
    const int wid  = tid >> 5;
    const int lane = tid & 31;

    const int base     = blockIdx.x * PPB;
    const int warpbase = base + wid * PPW;
    const int idx0     = warpbase + lane * PPT;

    const int b  = idx0 / HW_;
    const int p0 = idx0 - b * HW_;
    const int y  = p0 / OW_;
    const float yf = (float)y;

    // ---- vector loads (cached: inputs stay L2-resident across graph replays) ----
    union F2 { float2 v; float a[2]; };
    F2 hm, sc0, sc1, o0;
    hm.v  = *(const float2*)(heatmap + idx0);
    const float* scp = scale + (size_t)b * (2 * HW_) + p0;
    sc0.v = *(const float2*)(scp);
    sc1.v = *(const float2*)(scp + HW_);
    o0.v  = *(const float2*)(offset + (size_t)b * (2 * HW_) + p0);

    F2 lm[10];
    const float* lmp = landmark + (size_t)b * (10 * HW_) + p0;
#pragma unroll
    for (int j = 0; j < 10; j++)
        lm[j].v = *(const float2*)(lmp + (size_t)j * HW_);

    // ---- per-pixel compute, stage boxes ----
    F2 kp;
    float s0q[PPT], s1q[PPT], y1q[PPT], x1q[PPT], mq[PPT];

    float* bs = buf[wid] + lane * (5 * PPT);     // 10 contiguous floats

#pragma unroll
    for (int q = 0; q < PPT; q++) {
        float s0 = __expf(sc0.a[q]) * 4.0f;
        float s1 = __expf(sc1.a[q]) * 4.0f;

        float y1_raw = (yf + o0.a[q] + 0.5f) * 4.0f - s0 * 0.5f;
        float y1c = fmaxf(y1_raw, 0.0f);
        float y1  = fminf(y1c, IN_H_);
        float x1  = fminf(y1c, IN_W_);
        float y2  = fminf(y1 + s0, IN_H_);
        float x2  = fminf(x1 + s1, IN_W_);

        float h = hm.a[q];
        float m = (h >= THRESH_) ? 1.0f : 0.0f;
        kp.a[q] = m;

        s0q[q] = s0; s1q[q] = s1; y1q[q] = y1; x1q[q] = x1; mq[q] = m;

        // stage box record (vector STS where alignment allows: bs 8B-aligned)
        float2* bq2 = (float2*)(bs + q * 5 + (q & 1));
        if (q == 0) {
            bq2[0] = make_float2(x1 * m, y1 * m);
            bq2[1] = make_float2(x2 * m, y2 * m);
            bs[4]  = h * m;
        } else {
            bs[5]  = x1 * m;
            bq2[0] = make_float2(y1 * m, x2 * m);
            bq2[1] = make_float2(y2 * m, h * m);
        }
    }

    // keep: coalesced STG.64
    *(float2*)(keep + idx0) = kp.v;

    __syncwarp();

    // ---- flush boxes: 80 float4 per warp (streaming: evict-first) ----
    {
        const float4* src = (const float4*)buf[wid];
        float4*       dst = (float4*)(boxes + (size_t)warpbase * 5);
        __stcs(dst + lane,      src[lane]);
        __stcs(dst + 32 + lane, src[32 + lane]);
        if (lane < 16) __stcs(dst + 64 + lane, src[64 + lane]);
    }

    __syncwarp();   // WAR: box region fully read before landmark overwrite

    // ---- stage landmarks into same buffer ----
    {
        float2* ls = (float2*)(buf[wid] + lane * (10 * PPT));  // 20 floats
#pragma unroll
        for (int q = 0; q < PPT; q++) {
            float s0 = s0q[q], s1 = s1q[q], y1 = y1q[q], x1 = x1q[q], m = mq[q];
#pragma unroll
            for (int j = 0; j < 10; j += 2) {
                float ly = fmaf(lm[j].a[q],     s0, y1) * m;
                float lx = fmaf(lm[j + 1].a[q], s1, x1) * m;
                ls[q * 5 + (j >> 1)] = make_float2(ly, lx);
            }
        }
    }

    __syncwarp();

    // ---- flush landmarks: 160 float4 per warp (streaming) ----
    {
        const float4* src = (const float4*)buf[wid];
        float4*       dst = (float4*)(lms + (size_t)warpbase * 10);
#pragma unroll
        for (int i = 0; i < 5; i++)
            __stcs(dst + i * 32 + lane, src[i * 32 + lane]);
    }
}

extern "C" void kernel_launch(void* const* d_in, const int* in_sizes, int n_in,
                              void* d_out, int out_size)
{
    const float* heatmap  = (const float*)d_in[0];
    const float* scale    = (const float*)d_in[1];
    const float* offset   = (const float*)d_in[2];
    const float* landmark = (const float*)d_in[3];

    float* out   = (float*)d_out;
    float* boxes = out;                          // [B,HW,5]
    float* lms   = out + (size_t)TOTAL_ * 5;     // [B,HW,10]
    float* keep  = out + (size_t)TOTAL_ * 15;    // [B,HW]

    int blocks = TOTAL_ / PPB;                   // 4800
    centerface_decode_kernel<<<blocks, NT>>>(heatmap, scale, offset, landmark,
                                             boxes, lms, keep);
}